// round 1
// baseline (speedup 1.0000x reference)
#include <cuda_runtime.h>
#include <math.h>

#define C_CLASSES 10000
#define K_PROTO   4
#define D_DIM     2048
#define N_PROTO   (C_CLASSES * K_PROTO)   // 40000
#define WARPS_PER_BLOCK 8
#define BLOCK1 (WARPS_PER_BLOCK * 32)     // 256

// scratch for per-prototype squared distances (no cudaMalloc allowed)
__device__ float g_dist[N_PROTO];

// Kernel 1: one warp per prototype. d[p] = sum_d (proto[p,d] - feat[d])^2
__global__ __launch_bounds__(BLOCK1) void dist_kernel(
    const float* __restrict__ proto, const float* __restrict__ feat) {
    __shared__ float4 sf[D_DIM / 4];   // 8 KB feature tile

    const int tid = threadIdx.x;
    const float4* __restrict__ f4 = reinterpret_cast<const float4*>(feat);
    for (int i = tid; i < D_DIM / 4; i += BLOCK1) sf[i] = f4[i];
    __syncthreads();

    const int warp = tid >> 5;
    const int lane = tid & 31;
    const int p = blockIdx.x * WARPS_PER_BLOCK + warp;
    if (p < N_PROTO) {
        const float4* __restrict__ pp =
            reinterpret_cast<const float4*>(proto + (size_t)p * D_DIM);
        float acc = 0.0f;
#pragma unroll
        for (int i = 0; i < 16; ++i) {       // 16 float4 per lane = 2048/ (32*4)
            float4 v = pp[lane + i * 32];
            float4 f = sf[lane + i * 32];
            float dx = v.x - f.x;
            float dy = v.y - f.y;
            float dz = v.z - f.z;
            float dw = v.w - f.w;
            acc += dx * dx + dy * dy + dz * dz + dw * dw;
        }
#pragma unroll
        for (int o = 16; o > 0; o >>= 1)
            acc += __shfl_xor_sync(0xFFFFFFFFu, acc, o);
        if (lane == 0) g_dist[p] = acc;
    }
}

// Kernel 2: single block. Stable logsumexp over logits = -d, then the loss.
__global__ __launch_bounds__(1024) void reduce_kernel(
    const int* __restrict__ label, float* __restrict__ out) {
    __shared__ float red[1024];
    const int tid = threadIdx.x;

    // pass 1: dmin (=> max logit = -dmin)
    float m = INFINITY;
    for (int i = tid; i < N_PROTO; i += 1024) m = fminf(m, g_dist[i]);
    red[tid] = m;
    __syncthreads();
#pragma unroll
    for (int s = 512; s > 0; s >>= 1) {
        if (tid < s) red[tid] = fminf(red[tid], red[tid + s]);
        __syncthreads();
    }
    const float dmin = red[0];
    __syncthreads();

    // pass 2: sum exp(dmin - d)   (all args <= 0, no overflow)
    float sum = 0.0f;
    for (int i = tid; i < N_PROTO; i += 1024) sum += expf(dmin - g_dist[i]);
    red[tid] = sum;
    __syncthreads();
#pragma unroll
    for (int s = 512; s > 0; s >>= 1) {
        if (tid < s) red[tid] += red[tid + s];
        __syncthreads();
    }

    if (tid == 0) {
        const float log_one = -dmin + logf(red[0]);
        const int lbl = *label;
        float prob = 0.0f;
#pragma unroll
        for (int k = 0; k < K_PROTO; ++k)
            prob += log_one + g_dist[lbl * K_PROTO + k];  // log_one - logits
        out[0] = prob;
    }
}

extern "C" void kernel_launch(void* const* d_in, const int* in_sizes, int n_in,
                              void* d_out, int out_size) {
    const float* feature = (const float*)d_in[0];
    const int*   label   = (const int*)d_in[1];
    const float* protos  = (const float*)d_in[2];
    float* out = (float*)d_out;

    const int grid1 = (N_PROTO + WARPS_PER_BLOCK - 1) / WARPS_PER_BLOCK; // 5000
    dist_kernel<<<grid1, BLOCK1>>>(protos, feature);
    reduce_kernel<<<1, 1024>>>(label, out);
}

// round 2
// speedup vs baseline: 1.0447x; 1.0447x over previous
#include <cuda_runtime.h>
#include <math.h>

#define C_CLASSES 10000
#define K_PROTO   4
#define D_DIM     2048
#define N_PROTO   (C_CLASSES * K_PROTO)   // 40000
#define WARPS_PER_BLOCK 8
#define BLOCK1 (WARPS_PER_BLOCK * 32)     // 256
#define GRID2 148
#define BLOCK2 256

// scratch (no cudaMalloc allowed) — statically initialized, reset by kernel 2's
// last block so every graph replay sees identical starting state.
__device__ float g_dist[N_PROTO];
__device__ float g_partial[GRID2];
__device__ int   g_min_bits = 0x7F800000;   // +inf (d >= 0, so int-min == float-min)
__device__ unsigned int g_ticket = 0;

// Kernel 1: one warp per prototype. d[p] = sum_d (proto[p,d] - feat[d])^2
// Also folds in the global min of all distances via atomicMin.
__global__ __launch_bounds__(BLOCK1) void dist_kernel(
    const float* __restrict__ proto, const float* __restrict__ feat) {
    __shared__ float4 sf[D_DIM / 4];   // 8 KB feature tile
    __shared__ float  wmin[WARPS_PER_BLOCK];

    const int tid = threadIdx.x;
    const float4* __restrict__ f4 = reinterpret_cast<const float4*>(feat);
    for (int i = tid; i < D_DIM / 4; i += BLOCK1) sf[i] = f4[i];
    __syncthreads();

    const int warp = tid >> 5;
    const int lane = tid & 31;
    const int p = blockIdx.x * WARPS_PER_BLOCK + warp;

    const float4* __restrict__ pp =
        reinterpret_cast<const float4*>(proto + (size_t)p * D_DIM);
    float acc = 0.0f;
#pragma unroll
    for (int i = 0; i < 16; ++i) {       // 16 float4 per lane = 2048/(32*4)
        float4 v = __ldcs(pp + lane + i * 32);   // streaming: read-once data
        float4 f = sf[lane + i * 32];
        float dx = v.x - f.x;
        float dy = v.y - f.y;
        float dz = v.z - f.z;
        float dw = v.w - f.w;
        acc += dx * dx + dy * dy + dz * dz + dw * dw;
    }
#pragma unroll
    for (int o = 16; o > 0; o >>= 1)
        acc += __shfl_xor_sync(0xFFFFFFFFu, acc, o);
    if (lane == 0) {
        g_dist[p] = acc;
        wmin[warp] = acc;
    }
    __syncthreads();
    if (tid == 0) {
        float m = wmin[0];
#pragma unroll
        for (int w = 1; w < WARPS_PER_BLOCK; ++w) m = fminf(m, wmin[w]);
        atomicMin(&g_min_bits, __float_as_int(m));
    }
}

// Kernel 2: full-chip sum of exp(dmin - d); last block finalizes + resets state.
__global__ __launch_bounds__(BLOCK2) void expsum_kernel(
    const int* __restrict__ label, float* __restrict__ out) {
    __shared__ float red[BLOCK2 / 32];
    __shared__ bool amLast;

    const int tid  = threadIdx.x;
    const int lane = tid & 31;
    const int warp = tid >> 5;
    const float dmin = __int_as_float(g_min_bits);

    float sum = 0.0f;
    for (int i = blockIdx.x * BLOCK2 + tid; i < N_PROTO; i += GRID2 * BLOCK2)
        sum += expf(dmin - g_dist[i]);
#pragma unroll
    for (int o = 16; o > 0; o >>= 1)
        sum += __shfl_xor_sync(0xFFFFFFFFu, sum, o);
    if (lane == 0) red[warp] = sum;
    __syncthreads();
    if (tid == 0) {
        float s = red[0];
#pragma unroll
        for (int w = 1; w < BLOCK2 / 32; ++w) s += red[w];
        g_partial[blockIdx.x] = s;
        __threadfence();
        unsigned int t = atomicAdd(&g_ticket, 1u);
        amLast = (t == GRID2 - 1);
    }
    __syncthreads();

    if (amLast && tid == 0) {
        // deterministic fixed-order sum of partials
        float total = 0.0f;
        for (int b = 0; b < GRID2; ++b) total += g_partial[b];
        const float log_one = -dmin + logf(total);
        const int lbl = *label;
        float prob = 0.0f;
#pragma unroll
        for (int k = 0; k < K_PROTO; ++k)
            prob += log_one + g_dist[lbl * K_PROTO + k];   // log_one - logits
        out[0] = prob;
        // reset for next graph replay
        g_ticket = 0;
        g_min_bits = 0x7F800000;
        __threadfence();
    }
}

extern "C" void kernel_launch(void* const* d_in, const int* in_sizes, int n_in,
                              void* d_out, int out_size) {
    const float* feature = (const float*)d_in[0];
    const int*   label   = (const int*)d_in[1];
    const float* protos  = (const float*)d_in[2];
    float* out = (float*)d_out;

    const int grid1 = N_PROTO / WARPS_PER_BLOCK;   // 5000
    dist_kernel<<<grid1, BLOCK1>>>(protos, feature);
    expsum_kernel<<<GRID2, BLOCK2>>>(label, out);
}